// round 1
// baseline (speedup 1.0000x reference)
#include <cuda_runtime.h>

// ConvLRULayer: y = irfft2(rfft2(pad(u)) * rfft2(pad(k)), ortho) cropped.
// Shapes: u,k (4,64,251,509) fp32 -> flatten B*C=256 images of 251x509.
// Pad sizes: Hp=256, Wp=512 (both powers of two).
// y = IFFT2_unnorm(F(u) F(k)) * 2^-25.5   (N = 2^17, ortho norms combined)

#define IMGS 256
#define HH   251
#define WW   509
#define HP   256
#define WP   512
#define NJ   257   // rfft half-spectrum columns
#define WPAD 260   // padded row stride (float2) -> 2080B, 32B-aligned tiles

// Scratch: half spectra of u and k (row FFTs), later reused for the
// column-transformed product (stage2 writes in place over g_Su).
__device__ float2 g_Su[IMGS * HH * WPAD];
__device__ float2 g_Sk[IMGS * HH * WPAD];
// Twiddle table: tw[r] = exp(-2*pi*i*r/512), r in [0,256)
__device__ float2 g_tw[256];

__global__ void init_tw_kernel() {
    int r = threadIdx.x;
    double ang = -2.0 * 3.14159265358979323846264338327950288 * (double)r / 512.0;
    g_tw[r] = make_float2((float)cos(ang), (float)sin(ang));
}

// Stockham radix-2 FFT of N=2^LOGN points in shared ping-pong buffers.
// dir = +1: forward (exp(-i)), dir = -1: inverse (exp(+i)), unnormalized.
// Twiddle lookup: stage s needs exp(-i*pi*m/Ns) = tw[m << (8-s)] for both
// N=256 and N=512 (same absolute angle grid on the 512-circle).
// All `nthreads` threads must call this (contains __syncthreads).
template <int LOGN>
__device__ __forceinline__ float2* fft_shared(float2* b0, float2* b1,
                                              const float2* tw,
                                              int tid, int nthreads, float dir) {
    const int N = 1 << LOGN;
    float2* src = b0;
    float2* dst = b1;
#pragma unroll
    for (int s = 0; s < LOGN; s++) {
        __syncthreads();
        const int Ns = 1 << s;
        for (int j = tid; j < (N >> 1); j += nthreads) {
            float2 v0 = src[j];
            float2 v1 = src[j + (N >> 1)];
            int m = j & (Ns - 1);
            float2 w = tw[m << (8 - s)];
            float wy = dir * w.y;
            float2 v1t = make_float2(v1.x * w.x - v1.y * wy,
                                     v1.x * wy + v1.y * w.x);
            int idx = ((j >> s) << (s + 1)) | m;
            dst[idx]      = make_float2(v0.x + v1t.x, v0.y + v1t.y);
            dst[idx + Ns] = make_float2(v0.x - v1t.x, v0.y - v1t.y);
        }
        float2* tmp = src; src = dst; dst = tmp;
    }
    __syncthreads();
    return src;
}

// Stage 1: per (image,row): pack z = u + i*k, FFT-512, Hermitian-split into
// the two half row-spectra Su, Sk (257 complex each, coalesced stores).
__global__ void __launch_bounds__(256) stage1_kernel(const float* __restrict__ u,
                                                     const float* __restrict__ kin) {
    __shared__ float2 sa[512];
    __shared__ float2 sb[512];
    __shared__ float2 stw[256];
    int t = threadIdx.x;
    stw[t] = g_tw[t];

    int blk = blockIdx.x;  // img*251 + h
    size_t ibase = (size_t)blk * WW;
    const float* ur = u + ibase;
    const float* kr = kin + ibase;
#pragma unroll
    for (int n = t; n < WP; n += 256) {
        float a = 0.f, b = 0.f;
        if (n < WW) { a = ur[n]; b = kr[n]; }
        sa[n] = make_float2(a, b);
    }

    float2* res = fft_shared<9>(sa, sb, stw, t, 256, 1.0f);

    size_t obase = (size_t)blk * WPAD;
    for (int j = t; j < NJ; j += 256) {
        float2 zp = res[j];
        float2 zm = res[(WP - j) & (WP - 1)];
        // U = (Z + conj(Z-)) / 2 ; K = (Z - conj(Z-)) / (2i)
        float2 U  = make_float2(0.5f * (zp.x + zm.x), 0.5f * (zp.y - zm.y));
        float2 Kv = make_float2(0.5f * (zp.y + zm.y), 0.5f * (zm.x - zp.x));
        g_Su[obase + j] = U;
        g_Sk[obase + j] = Kv;
    }
}

// Stage 2: per (image, 4-column tile): forward FFT-256 of the 4 Su columns
// and 4 Sk columns concurrently (8 groups x 128 butterflies = 1024 threads),
// pointwise multiply with combined ortho scale, inverse FFT-256 of the 4
// product columns, write back in place (rows h<251 only -- rest is cropped).
__global__ void __launch_bounds__(1024) stage2_kernel() {
    __shared__ float2 sbuf[2][8][256];  // [pingpong][group][elem] = 32KB
    __shared__ float2 stw[256];
    int t = threadIdx.x;
    if (t < 256) stw[t] = g_tw[t];

    int img = blockIdx.y;
    int j0  = blockIdx.x * 4;
    int c = t & 3;        // column within tile
    int h = t >> 2;       // 0..255
    int j = j0 + c;
    bool valid = (j < NJ) && (h < HH);
    size_t gidx = ((size_t)img * HH + h) * WPAD + j;
    float2 zv = make_float2(0.f, 0.f);
    sbuf[0][c][h]     = valid ? g_Su[gidx] : zv;   // zero-pad h>=251
    sbuf[0][4 + c][h] = valid ? g_Sk[gidx] : zv;

    int g  = t >> 7;   // group 0..7 (0-3: u cols, 4-7: k cols)
    int jj = t & 127;  // butterfly within group

    // forward FFT-256 on all 8 groups, lockstep stages
    int pp = 0;
#pragma unroll
    for (int s = 0; s < 8; s++) {
        __syncthreads();
        int Ns = 1 << s;
        float2* src = sbuf[pp][g];
        float2* dst = sbuf[pp ^ 1][g];
        float2 v0 = src[jj];
        float2 v1 = src[jj + 128];
        int m = jj & (Ns - 1);
        float2 w = stw[m << (8 - s)];
        float2 v1t = make_float2(v1.x * w.x - v1.y * w.y,
                                 v1.x * w.y + v1.y * w.x);
        int idx = ((jj >> s) << (s + 1)) | m;
        dst[idx]      = make_float2(v0.x + v1t.x, v0.y + v1t.y);
        dst[idx + Ns] = make_float2(v0.x - v1t.x, v0.y - v1t.y);
        pp ^= 1;
    }
    __syncthreads();  // pp == 0: results in buffer 0

    // pointwise product, scaled by N^-1.5 = 2^-25.5
    const float SCALE = 2.1073424255447017e-08f;
    float2 a = sbuf[0][c][h];
    float2 b = sbuf[0][4 + c][h];
    float2 p = make_float2((a.x * b.x - a.y * b.y) * SCALE,
                           (a.x * b.y + a.y * b.x) * SCALE);
    sbuf[0][c][h] = p;   // each thread owns exactly this element

    // inverse FFT-256 on groups 0..3 (product columns)
    pp = 0;
#pragma unroll
    for (int s = 0; s < 8; s++) {
        __syncthreads();
        if (t < 512) {
            int Ns = 1 << s;
            float2* src = sbuf[pp][g];
            float2* dst = sbuf[pp ^ 1][g];
            float2 v0 = src[jj];
            float2 v1 = src[jj + 128];
            int m = jj & (Ns - 1);
            float2 w = stw[m << (8 - s)];
            float wy = -w.y;  // conj -> inverse
            float2 v1t = make_float2(v1.x * w.x - v1.y * wy,
                                     v1.x * wy + v1.y * w.x);
            int idx = ((jj >> s) << (s + 1)) | m;
            dst[idx]      = make_float2(v0.x + v1t.x, v0.y + v1t.y);
            dst[idx + Ns] = make_float2(v0.x - v1t.x, v0.y - v1t.y);
        }
        pp ^= 1;
    }
    __syncthreads();

    if (valid) g_Su[gidx] = sbuf[0][c][h];
}

// Stage 3: per (image, output row h<251): load 257 product values (coalesced),
// Hermitian-extend to 512 in smem, inverse FFT-512, write real part (509 cols).
__global__ void __launch_bounds__(256) stage3_kernel(float* __restrict__ out) {
    __shared__ float2 sa[512];
    __shared__ float2 sb[512];
    __shared__ float2 stw[256];
    int t = threadIdx.x;
    stw[t] = g_tw[t];

    int blk = blockIdx.x;  // img*251 + h
    size_t ibase = (size_t)blk * WPAD;
    for (int n = t; n < NJ; n += 256) {
        sa[n] = g_Su[ibase + n];
    }
    __syncthreads();
    for (int n = NJ + t; n < WP; n += 256) {  // mirror: conj of sa[512-n]
        float2 v = sa[WP - n];
        sa[n] = make_float2(v.x, -v.y);
    }

    float2* res = fft_shared<9>(sa, sb, stw, t, 256, -1.0f);

    size_t obase = (size_t)blk * WW;
    for (int n = t; n < WW; n += 256) {
        out[obase + n] = res[n].x;
    }
}

extern "C" void kernel_launch(void* const* d_in, const int* in_sizes, int n_in,
                              void* d_out, int out_size) {
    const float* u  = (const float*)d_in[0];
    const float* kk = (const float*)d_in[1];
    float* out = (float*)d_out;

    init_tw_kernel<<<1, 256>>>();
    stage1_kernel<<<IMGS * HH, 256>>>(u, kk);
    stage2_kernel<<<dim3((NJ + 3) / 4, IMGS), 1024>>>();
    stage3_kernel<<<IMGS * HH, 256>>>(out);
}

// round 2
// speedup vs baseline: 3.6387x; 3.6387x over previous
#include <cuda_runtime.h>

// y = irfft2(rfft2(pad(u)) * rfft2(pad(k)), ortho) cropped.
// (4,64,251,509) fp32 -> 256 images 251x509, pad to 256x512 (powers of 2).
// Combined ortho scale: N^-1.5 = 2^-25.5, applied once at the product.
//
// All FFTs are register-resident four-step decompositions:
//   FFT-512 = 8x8x8  (64 thr x 8 regs, 2 smem exchanges)
//   FFT-256 = 16x16  (16 thr x 16 regs, 1 smem exchange)

#define IMGS 256
#define HH   251
#define WW   509
#define WP   512
#define NJ   257
#define WPAD 260   // float2 row stride of spectral scratch
#define P512 72    // padded k1-row stride for the 512 exchange (conflict-free)

__device__ float2 g_Su[IMGS * HH * WPAD];
__device__ float2 g_Sk[IMGS * HH * WPAD];
__device__ float2 g_tw[512];   // tw[r] = exp(-2*pi*i*r/512)

__global__ void init_tw_kernel() {
    int r = threadIdx.x;
    double ang = -2.0 * 3.141592653589793238462643383279502884 * (double)r / 512.0;
    g_tw[r] = make_float2((float)cos(ang), (float)sin(ang));
}

__device__ __forceinline__ float2 cmul(float2 a, float2 b) {
    return make_float2(a.x*b.x - a.y*b.y, a.x*b.y + a.y*b.x);
}
__device__ __forceinline__ float2 cadd(float2 a, float2 b) { return make_float2(a.x+b.x, a.y+b.y); }
__device__ __forceinline__ float2 csub(float2 a, float2 b) { return make_float2(a.x-b.x, a.y-b.y); }
// multiply by -i (DIR=+1 forward) or +i (DIR=-1 inverse)
template<int DIR>
__device__ __forceinline__ float2 mulmi(float2 v) {
    return (DIR == 1) ? make_float2(v.y, -v.x) : make_float2(-v.y, v.x);
}

// 8-point DFT, natural-order in/out, DIF internally.
template<int DIR>
__device__ __forceinline__ void dft8(float2 x[8]) {
    const float C = 0.70710678118654752f;
    float2 t0 = cadd(x[0], x[4]), t4 = csub(x[0], x[4]);
    float2 t1 = cadd(x[1], x[5]), t5 = csub(x[1], x[5]);
    float2 t2 = cadd(x[2], x[6]), t6 = csub(x[2], x[6]);
    float2 t3 = cadd(x[3], x[7]), t7 = csub(x[3], x[7]);
    t5 = cmul(t5, make_float2(C, -DIR * C));     // W8^1
    t6 = mulmi<DIR>(t6);                          // W8^2
    t7 = cmul(t7, make_float2(-C, -DIR * C));    // W8^3
    // even outputs: DFT4 of (t0..t3)
    float2 p0 = cadd(t0, t2), q0 = csub(t0, t2);
    float2 p1 = cadd(t1, t3), q1 = mulmi<DIR>(csub(t1, t3));
    x[0] = cadd(p0, p1); x[4] = csub(p0, p1);
    x[2] = cadd(q0, q1); x[6] = csub(q0, q1);
    // odd outputs: DFT4 of (t4..t7)
    float2 r0 = cadd(t4, t6), s0 = csub(t4, t6);
    float2 r1 = cadd(t5, t7), s1 = mulmi<DIR>(csub(t5, t7));
    x[1] = cadd(r0, r1); x[5] = csub(r0, r1);
    x[3] = cadd(s0, s1); x[7] = csub(s0, s1);
}

// 16-point DFT, natural-order in/out (4x4 four-step in registers).
template<int DIR>
__device__ __forceinline__ void dft16(float2 x[16]) {
    float2 y[16];
#pragma unroll
    for (int b = 0; b < 4; b++) {
        float2 a0 = x[b], a1 = x[b + 4], a2 = x[b + 8], a3 = x[b + 12];
        float2 t0 = cadd(a0, a2), t1 = csub(a0, a2);
        float2 t2 = cadd(a1, a3), t3 = mulmi<DIR>(csub(a1, a3));
        y[b*4 + 0] = cadd(t0, t2);
        y[b*4 + 1] = cadd(t1, t3);
        y[b*4 + 2] = csub(t0, t2);
        y[b*4 + 3] = csub(t1, t3);
    }
    const float c1 = 0.9238795325112867f, s1 = 0.3826834323650898f;
    const float C = 0.70710678118654752f;
    const float2 w1 = make_float2(c1, -DIR * s1);
    const float2 w2 = make_float2(C, -DIR * C);
    const float2 w3 = make_float2(s1, -DIR * c1);
    const float2 w4 = make_float2(0.f, (float)(-DIR));
    const float2 w6 = make_float2(-C, -DIR * C);
    const float2 w9 = make_float2(-c1, DIR * s1);
    y[5]  = cmul(y[5],  w1); y[6]  = cmul(y[6],  w2); y[7]  = cmul(y[7],  w3);
    y[9]  = cmul(y[9],  w2); y[10] = cmul(y[10], w4); y[11] = cmul(y[11], w6);
    y[13] = cmul(y[13], w3); y[14] = cmul(y[14], w6); y[15] = cmul(y[15], w9);
#pragma unroll
    for (int k1 = 0; k1 < 4; k1++) {
        float2 a0 = y[k1], a1 = y[4 + k1], a2 = y[8 + k1], a3 = y[12 + k1];
        float2 t0 = cadd(a0, a2), t1 = csub(a0, a2);
        float2 t2 = cadd(a1, a3), t3 = mulmi<DIR>(csub(a1, a3));
        x[0*4 + k1] = cadd(t0, t2);
        x[1*4 + k1] = cadd(t1, t3);
        x[2*4 + k1] = csub(t0, t2);
        x[3*4 + k1] = csub(t1, t3);
    }
}

// FFT-512 core: 64 threads (t in [0,64)), x holds x[n1*64+t] on entry.
// On exit x[q2] = X[q2*64 + t]. Uses s[8*P512] smem; internally synced
// (block-wide __syncthreads; all rows in block run lockstep).
template<int DIR>
__device__ __forceinline__ void fft512_core(float2 x[8], float2* s, int t) {
    dft8<DIR>(x);
    float2 w = g_tw[t];
    if (DIR < 0) w.y = -w.y;
    float2 cw = w;
#pragma unroll
    for (int k1 = 1; k1 < 8; k1++) { x[k1] = cmul(x[k1], cw); cw = cmul(cw, w); }
#pragma unroll
    for (int k1 = 0; k1 < 8; k1++) s[k1 * P512 + t] = x[k1];
    __syncthreads();
    int k1 = t >> 3, m2 = t & 7;
#pragma unroll
    for (int m1 = 0; m1 < 8; m1++) x[m1] = s[k1 * P512 + m1 * 8 + m2];
    __syncthreads();
    dft8<DIR>(x);
    w = g_tw[8 * m2];
    if (DIR < 0) w.y = -w.y;
    cw = w;
#pragma unroll
    for (int q1 = 1; q1 < 8; q1++) { x[q1] = cmul(x[q1], cw); cw = cmul(cw, w); }
#pragma unroll
    for (int q1 = 0; q1 < 8; q1++) s[k1 * P512 + q1 * 8 + m2] = x[q1];
    __syncthreads();
    int k1c = t & 7, q1c = t >> 3;
#pragma unroll
    for (int m = 0; m < 8; m++) x[m] = s[k1c * P512 + q1c * 8 + m];
    __syncthreads();
    dft8<DIR>(x);
    // output index q2*64 + q1c*8 + k1c == q2*64 + t
}

// FFT-256 core: 16 threads per column (role q), column c, x holds
// x[n1*16 + q] on entry; on exit x[k2] = X[k2*16 + q]. E = exchange buffer.
template<int DIR>
__device__ __forceinline__ void fft256_core(float2 x[16], float2* E, int c, int q) {
    dft16<DIR>(x);
    float2 w = g_tw[2 * q];
    if (DIR < 0) w.y = -w.y;
    float2 cw = w;
#pragma unroll
    for (int k1 = 1; k1 < 16; k1++) { x[k1] = cmul(x[k1], cw); cw = cmul(cw, w); }
#pragma unroll
    for (int k1 = 0; k1 < 16; k1++) E[c * 272 + k1 * 17 + q] = x[k1];
    __syncthreads();
#pragma unroll
    for (int n2 = 0; n2 < 16; n2++) x[n2] = E[c * 272 + q * 17 + n2];
    __syncthreads();
    dft16<DIR>(x);
}

// Stage 1: per row: pack z=u+ik, FFT-512 fwd, Hermitian split -> g_Su/g_Sk.
__global__ void __launch_bounds__(256) stage1_kernel(const float* __restrict__ u,
                                                     const float* __restrict__ kin) {
    __shared__ float2 sm[4][8 * P512];
    int t = threadIdx.x & 63;
    int r = threadIdx.x >> 6;
    int row = blockIdx.x * 4 + r;       // img*251 + h
    size_t ibase = (size_t)row * WW;
    float2 x[8];
#pragma unroll
    for (int a = 0; a < 8; a++) {
        int n = a * 64 + t;
        float ur = 0.f, kr = 0.f;
        if (n < WW) { ur = u[ibase + n]; kr = kin[ibase + n]; }
        x[a] = make_float2(ur, kr);
    }
    float2* s = sm[r];
    fft512_core<1>(x, s, t);
#pragma unroll
    for (int q2 = 0; q2 < 8; q2++) s[q2 * 64 + t] = x[q2];
    __syncthreads();
    size_t obase = (size_t)row * WPAD;
#pragma unroll
    for (int jj = 0; jj < 5; jj++) {
        int j = t + jj * 64;
        if (j <= 256) {
            float2 zp = s[j];
            float2 zm = s[(512 - j) & 511];
            g_Su[obase + j] = make_float2(0.5f * (zp.x + zm.x), 0.5f * (zp.y - zm.y));
            g_Sk[obase + j] = make_float2(0.5f * (zp.y + zm.y), 0.5f * (zm.x - zp.x));
        }
    }
}

// Stage 2: per (image, 16-column tile): fwd FFT-256 of U and K columns,
// pointwise product with ortho scale, inverse FFT-256, write back over g_Su.
// Dynamic smem: A (staging/exchange, 4352 f2) + Ubuf (4352 f2) = 68 KB.
__global__ void __launch_bounds__(256) stage2_kernel() {
    extern __shared__ float2 dsm[];
    float2* A    = dsm;
    float2* Ubuf = dsm + 4352;
    const int t = threadIdx.x;
    const int c = t >> 4;      // column within tile (FFT role) / staging row hh
    const int q = t & 15;      // within-column role (FFT) / staging column cc
    const int img = blockIdx.y;
    const int j0  = blockIdx.x * 16;
    const size_t base = (size_t)img * HH * WPAD + j0;
    const bool cval = (j0 + q) < NJ;   // staging-column validity

    float2 x[16];

    // ---- stage U columns (global row-major -> smem tile [h][cc]) ----
#pragma unroll
    for (int m = 0; m < 16; m++) {
        int h = c + 16 * m;
        float2 v = make_float2(0.f, 0.f);
        if (h < HH && cval) v = g_Su[base + (size_t)h * WPAD + q];
        A[h * 17 + q] = v;
    }
    __syncthreads();
#pragma unroll
    for (int n1 = 0; n1 < 16; n1++) x[n1] = A[(n1 * 16 + q) * 17 + c];
    __syncthreads();
    fft256_core<1>(x, A, c, q);
#pragma unroll
    for (int k2 = 0; k2 < 16; k2++) Ubuf[c * 272 + q * 17 + k2] = x[k2];

    // ---- stage K columns ----
#pragma unroll
    for (int m = 0; m < 16; m++) {
        int h = c + 16 * m;
        float2 v = make_float2(0.f, 0.f);
        if (h < HH && cval) v = g_Sk[base + (size_t)h * WPAD + q];
        A[h * 17 + q] = v;
    }
    __syncthreads();
#pragma unroll
    for (int n1 = 0; n1 < 16; n1++) x[n1] = A[(n1 * 16 + q) * 17 + c];
    __syncthreads();
    fft256_core<1>(x, A, c, q);

    // ---- pointwise product, combined ortho scale 2^-25.5 ----
    const float SCALE = 2.1073424255447017e-08f;
#pragma unroll
    for (int k2 = 0; k2 < 16; k2++) {
        float2 p = cmul(x[k2], Ubuf[c * 272 + q * 17 + k2]);
        x[k2] = make_float2(p.x * SCALE, p.y * SCALE);
    }

    // ---- inverse FFT-256 (input index k2*16+q == n1'*16+n2' directly) ----
    fft256_core<-1>(x, A, c, q);

    // ---- stage out: smem tile [h][c] -> coalesced global writes ----
#pragma unroll
    for (int k2 = 0; k2 < 16; k2++) A[(k2 * 16 + q) * 17 + c] = x[k2];
    __syncthreads();
#pragma unroll
    for (int m = 0; m < 16; m++) {
        int h = c + 16 * m;
        if (h < HH && cval) g_Su[base + (size_t)h * WPAD + q] = A[h * 17 + q];
    }
}

// Stage 3: per output row: Hermitian-extend 257->512, inverse FFT-512,
// write real part of first 509 samples (coalesced: n = q2*64 + t).
__global__ void __launch_bounds__(256) stage3_kernel(float* __restrict__ out) {
    __shared__ float2 sm[4][8 * P512];
    int t = threadIdx.x & 63;
    int r = threadIdx.x >> 6;
    int row = blockIdx.x * 4 + r;
    float2* s = sm[r];
    size_t ibase = (size_t)row * WPAD;
#pragma unroll
    for (int jj = 0; jj < 5; jj++) {
        int j = t + jj * 64;
        if (j <= 256) s[j] = g_Su[ibase + j];
    }
    __syncthreads();
#pragma unroll
    for (int jj = 0; jj < 4; jj++) {
        int n = 257 + t + jj * 64;
        if (n < 512) { float2 v = s[512 - n]; s[n] = make_float2(v.x, -v.y); }
    }
    __syncthreads();
    float2 x[8];
#pragma unroll
    for (int a = 0; a < 8; a++) x[a] = s[a * 64 + t];
    __syncthreads();
    fft512_core<-1>(x, s, t);
    size_t obase = (size_t)row * WW;
#pragma unroll
    for (int q2 = 0; q2 < 8; q2++) {
        int n = q2 * 64 + t;
        if (n < WW) out[obase + n] = x[q2].x;
    }
}

extern "C" void kernel_launch(void* const* d_in, const int* in_sizes, int n_in,
                              void* d_out, int out_size) {
    const float* u  = (const float*)d_in[0];
    const float* kk = (const float*)d_in[1];
    float* out = (float*)d_out;

    cudaFuncSetAttribute(stage2_kernel,
                         cudaFuncAttributeMaxDynamicSharedMemorySize, 69632);

    init_tw_kernel<<<1, 512>>>();
    stage1_kernel<<<16064, 256>>>(u, kk);                 // 64256 rows / 4
    stage2_kernel<<<dim3(17, IMGS), 256, 69632>>>();      // 17 tiles x 256 imgs
    stage3_kernel<<<16064, 256>>>(out);
}